// round 11
// baseline (speedup 1.0000x reference)
#include <cuda_runtime.h>
#include <cuda_bf16.h>
#include <cstdint>
#include <cfloat>
#include <math.h>

#define Bc 2
#define Tc 1024
#define Dc 1024
#define Hc 16
#define DHc 64
#define Rc 32
#define Lc 2
#define FFc 4096
#define OVc 16384
#define QS 3072
#define BT (Bc*Tc)
#define DD (Dc*Dc)

// ---------------- static device scratch ----------------
__device__ float g_delta[Bc*Tc*Rc];
__device__ float g_cos[Bc*Tc*Rc];
__device__ float g_sin[Bc*Tc*Rc];
__device__ float g_x  [BT*Dc];
__device__ float g_qkv[BT*QS];
__device__ float g_sc [(size_t)Bc*Hc*Tc*Tc];     // fp32 scores

// packed bf16x2 hi/lo operand arrays (pair = 2 consecutive K elements)
__device__ uint32_t g_hhi[BT*512],  g_hlo[BT*512];
__device__ uint32_t g_qhi[BT*512],  g_qlo[BT*512];
__device__ uint32_t g_khi[BT*512],  g_klo[BT*512];
__device__ uint32_t g_vthi[Bc*Hc*DHc*512], g_vtlo[Bc*Hc*DHc*512];
__device__ uint32_t g_schi[(size_t)Bc*Hc*Tc*512], g_sclo[(size_t)Bc*Hc*Tc*512];
__device__ uint32_t g_ohi[BT*512],  g_olo[BT*512];
__device__ uint32_t g_ffhi[BT*2048], g_fflo[BT*2048];
__device__ uint32_t g_whi[20*DD], g_wlo[20*DD];
__device__ float    g_bqkv[Lc*QS];

#define P_QKV 0
#define P_WO  ((size_t)3072*512)
#define P_W1  (P_WO + (size_t)1024*512)
#define P_W2  (P_W1 + (size_t)4096*512)
#define PL_SZ (P_W2 + (size_t)1024*2048)
#define P_OUT (2*PL_SZ)
#define WPL(l) ((size_t)(l)*PL_SZ)

// ---------------- helpers ----------------
__device__ __forceinline__ uint32_t smem_u32(const void* p) {
    uint32_t a;
    asm("{ .reg .u64 t; cvta.to.shared.u64 t, %1; cvt.u32.u64 %0, t; }" : "=r"(a) : "l"(p));
    return a;
}
__device__ __forceinline__ void bsplit2(float x0, float x1, uint32_t& hi, uint32_t& lo) {
    unsigned short h0 = __bfloat16_as_ushort(__float2bfloat16_rn(x0));
    unsigned short h1 = __bfloat16_as_ushort(__float2bfloat16_rn(x1));
    float r0 = x0 - __uint_as_float(((uint32_t)h0) << 16);
    float r1 = x1 - __uint_as_float(((uint32_t)h1) << 16);
    unsigned short l0 = __bfloat16_as_ushort(__float2bfloat16_rn(r0));
    unsigned short l1 = __bfloat16_as_ushort(__float2bfloat16_rn(r1));
    hi = ((uint32_t)h1 << 16) | h0;
    lo = ((uint32_t)l1 << 16) | l0;
}
__device__ __forceinline__ void cp16(uint32_t dst, const void* src) {
    asm volatile("cp.async.cg.shared.global [%0], [%1], 16;" :: "r"(dst), "l"(src) : "memory");
}
#define CP_COMMIT() asm volatile("cp.async.commit_group;" ::: "memory")
#define CP_WAIT1()  asm volatile("cp.async.wait_group 1;" ::: "memory")
#define CP_WAIT0()  asm volatile("cp.async.wait_group 0;" ::: "memory")

#define MMA16(d, a, b) \
    asm volatile("mma.sync.aligned.m16n8k16.row.col.f32.bf16.bf16.f32 " \
        "{%0,%1,%2,%3}, {%4,%5,%6,%7}, {%8,%9}, {%0,%1,%2,%3};" \
        : "+f"((d)[0]), "+f"((d)[1]), "+f"((d)[2]), "+f"((d)[3]) \
        : "r"((a)[0]), "r"((a)[1]), "r"((a)[2]), "r"((a)[3]), "r"((b)[0]), "r"((b)[1]))

#define LDSM4(r, addr) \
    asm volatile("ldmatrix.sync.aligned.m8n8.x4.shared.b16 {%0,%1,%2,%3}, [%4];" \
        : "=r"((r)[0]), "=r"((r)[1]), "=r"((r)[2]), "=r"((r)[3]) : "r"(addr))

// ================= 3xBF16 mma.sync GEMM (pre-split + ldmatrix) =================
// C[M,N] = A[M,K] * Bt[N,K]^T, A/B packed bf16x2 hi/lo, strides in PAIR units.
// 128 x NT tiles, K-chunk 16, double-buffered cp.async.
// MODE 0: fp32 out (+bias if non-null) | 1: fp32 +bias+residual
//      2: packed gelu(+bias) out      | 3: packed plain out
// CSKIP: skip tiles above diagonal. CKLIM: clamp K at bm+128.
template<int NT, int MODE, bool CSKIP, bool CKLIM>
__global__ void __launch_bounds__(256)
mma_gemm(const uint32_t* __restrict__ AhG, const uint32_t* __restrict__ AlG,
         const uint32_t* __restrict__ BhG, const uint32_t* __restrict__ BlG,
         const float* __restrict__ bias, const float* __restrict__ Res,
         float* __restrict__ C, uint32_t* __restrict__ Chi, uint32_t* __restrict__ Clo,
         int M, int N, int K, int ldaP, int ldbP, int ldc,
         int H2, long long sAb, long long sAh, long long sBb, long long sBh,
         long long sCb, long long sCh)
{
    int bm = blockIdx.y * 128, bn = blockIdx.x * NT;
    if (CSKIP && bn > bm) return;

    int z = blockIdx.z;
    int zb = z / H2, zh = z % H2;
    AhG += zb * sAb + zh * sAh;  AlG += zb * sAb + zh * sAh;
    BhG += zb * sBb + zh * sBh;  BlG += zb * sBb + zh * sBh;
    const float* R0 = nullptr;
    if (MODE == 0 || MODE == 1) {
        C += zb * sCb + zh * sCh;
        if (MODE == 1) R0 = Res + zb * sCb + zh * sCh;
    } else {
        Chi += zb * sCb + zh * sCh;
        Clo += zb * sCb + zh * sCh;
    }

    extern __shared__ uint32_t sm[];
    const int AST = 128 * 12;
    const int BST = NT * 12;
    uint32_t* AsHi = sm;
    uint32_t* AsLo = sm + 2 * AST;
    uint32_t* BsHi = sm + 4 * AST;
    uint32_t* BsLo = BsHi + 2 * BST;

    int tid = threadIdx.x;
    int w = tid >> 5, lane = tid & 31;
    int wm = w & 1, wn = w >> 1;
    int g = lane >> 2, tg = lane & 3;
    const int NTILES = NT / 32;

    int Keff = K;
    if (CKLIM) { int kl = bm + 128; Keff = (kl < K) ? kl : K; }
    int NCH = Keff >> 4;

    float acc[4][NTILES][4];
    #pragma unroll
    for (int i = 0; i < 4; i++)
        #pragma unroll
        for (int j = 0; j < NTILES; j++)
            #pragma unroll
            for (int e = 0; e < 4; e++) acc[i][j][e] = 0.f;

    auto copy_chunk = [&](int c, int s) {
        int row = tid >> 1, seg = tid & 1;
        size_t ga = (size_t)(bm + row) * ldaP + c * 8 + seg * 4;
        uint32_t da = s * AST + row * 12 + seg * 4;
        cp16(smem_u32(AsHi + da), AhG + ga);
        cp16(smem_u32(AsLo + da), AlG + ga);
        if (NT == 128 || tid < 2 * NT) {
            size_t gb = (size_t)(bn + row) * ldbP + c * 8 + seg * 4;
            uint32_t db = s * BST + row * 12 + seg * 4;
            cp16(smem_u32(BsHi + db), BhG + gb);
            cp16(smem_u32(BsLo + db), BlG + gb);
        }
        CP_COMMIT();
    };

    copy_chunk(0, 0);
    if (NCH > 1) copy_chunk(1, 1);

    // ldmatrix per-lane byte offsets
    const uint32_t uAsHi = smem_u32(AsHi), uAsLo = smem_u32(AsLo);
    const uint32_t uBsHi = smem_u32(BsHi), uBsLo = smem_u32(BsLo);
    const int laneA = (((lane & 15) + wm * 64) * 12 + (lane >> 4) * 4) * 4;
    const int laneB = ((((lane & 7) + ((lane >> 4) << 3)) + wn * (NT / 4)) * 12
                       + ((lane >> 3) & 1) * 4) * 4;

    for (int c = 0; c < NCH; c++) {
        if (c + 1 < NCH) { CP_WAIT1(); } else { CP_WAIT0(); }
        __syncthreads();
        int s = c & 1;
        int sa = s * AST * 4;
        int sb = s * BST * 4;

        uint32_t ah[4][4], al[4][4];
        #pragma unroll
        for (int mt = 0; mt < 4; mt++) {
            int off = sa + mt * (16 * 12 * 4) + laneA;
            LDSM4(ah[mt], uAsHi + off);
            LDSM4(al[mt], uAsLo + off);
        }
        uint32_t bh4[2 * NTILES], bl4[2 * NTILES];
        #pragma unroll
        for (int j = 0; j < NTILES / 2; j++) {
            int off = sb + j * (16 * 12 * 4) + laneB;
            LDSM4(bh4 + 4 * j, uBsHi + off);
            LDSM4(bl4 + 4 * j, uBsLo + off);
        }
        #pragma unroll
        for (int mt = 0; mt < 4; mt++)
            #pragma unroll
            for (int nt = 0; nt < NTILES; nt++) {
                MMA16(acc[mt][nt], ah[mt], bl4 + 2 * nt);
                MMA16(acc[mt][nt], al[mt], bh4 + 2 * nt);
                MMA16(acc[mt][nt], ah[mt], bh4 + 2 * nt);
            }
        __syncthreads();
        if (c + 2 < NCH) copy_chunk(c + 2, s);
    }

    // -------- epilogue --------
    #pragma unroll
    for (int mt = 0; mt < 4; mt++) {
        #pragma unroll
        for (int nt = 0; nt < NTILES; nt++) {
            int row0 = bm + wm * 64 + mt * 16 + g;
            int col  = bn + wn * (NT / 4) + nt * 8 + tg * 2;
            #pragma unroll
            for (int half = 0; half < 2; half++) {
                int row = row0 + half * 8;
                float v0 = acc[mt][nt][half * 2 + 0];
                float v1 = acc[mt][nt][half * 2 + 1];
                if (MODE == 1 || MODE == 2 || (MODE == 0 && bias)) {
                    float2 bv = *(const float2*)(bias + col);
                    v0 += bv.x; v1 += bv.y;
                }
                if (MODE == 1) {
                    float2 rr = *(const float2*)(R0 + (size_t)row * ldc + col);
                    v0 += rr.x; v1 += rr.y;
                }
                if (MODE == 2) {
                    v0 = 0.5f * v0 * (1.f + erff(v0 * 0.70710678118654752f));
                    v1 = 0.5f * v1 * (1.f + erff(v1 * 0.70710678118654752f));
                }
                if (MODE == 0 || MODE == 1) {
                    float2 o = {v0, v1};
                    *(float2*)(C + (size_t)row * ldc + col) = o;
                } else {
                    uint32_t hi, lo;
                    bsplit2(v0, v1, hi, lo);
                    size_t ci = (size_t)row * ldc + (col >> 1);
                    Chi[ci] = hi;
                    Clo[ci] = lo;
                }
            }
        }
    }
}

// ---------------- transpose + split ----------------
__global__ void tsplit_kernel(const float* __restrict__ in,
                              uint32_t* __restrict__ ohi, uint32_t* __restrict__ olo,
                              int rows, int cols) {
    __shared__ float tile[32][33];
    int c0 = blockIdx.x * 32, r0 = blockIdx.y * 32;
    int x = threadIdx.x, y = threadIdx.y;
    float4 v = *(const float4*)(in + (size_t)(r0 + y) * cols + c0 + 4 * x);
    tile[y][4*x+0] = v.x; tile[y][4*x+1] = v.y; tile[y][4*x+2] = v.z; tile[y][4*x+3] = v.w;
    __syncthreads();
    int rowP = rows >> 1;
    uint32_t h0, l0, h1, l1;
    bsplit2(tile[4*x+0][y], tile[4*x+1][y], h0, l0);
    bsplit2(tile[4*x+2][y], tile[4*x+3][y], h1, l1);
    size_t ob = (size_t)(c0 + y) * rowP + (r0 >> 1) + 2 * x;
    *(uint2*)(ohi + ob) = make_uint2(h0, h1);
    *(uint2*)(olo + ob) = make_uint2(l0, l1);
}

__global__ void vtrans_kernel(const float* __restrict__ qkv,
                              uint32_t* __restrict__ vthi, uint32_t* __restrict__ vtlo) {
    __shared__ float tile[32][33];
    int z = blockIdx.z, b = z >> 4, hh = z & 15;
    int t0 = blockIdx.x * 32, d0 = blockIdx.y * 32;
    int x = threadIdx.x, y = threadIdx.y;
    float4 v = *(const float4*)(qkv + (size_t)(b * Tc + t0 + y) * QS + 2 * Dc + hh * DHc + d0 + 4 * x);
    tile[y][4*x+0] = v.x; tile[y][4*x+1] = v.y; tile[y][4*x+2] = v.z; tile[y][4*x+3] = v.w;
    __syncthreads();
    uint32_t h0, l0, h1, l1;
    bsplit2(tile[4*x+0][y], tile[4*x+1][y], h0, l0);
    bsplit2(tile[4*x+2][y], tile[4*x+3][y], h1, l1);
    size_t ob = (size_t)(z * DHc + d0 + y) * 512 + (t0 >> 1) + 2 * x;
    *(uint2*)(vthi + ob) = make_uint2(h0, h1);
    *(uint2*)(vtlo + ob) = make_uint2(l0, l1);
}

__global__ void packbias_kernel(const float* __restrict__ bq,
                                const float* __restrict__ bk,
                                const float* __restrict__ bv,
                                float* __restrict__ out) {
    int l = blockIdx.y;
    int i = blockIdx.x * 256 + threadIdx.x;
    float v = (i < Dc) ? bq[l * Dc + i] : (i < 2 * Dc) ? bk[l * Dc + i - Dc] : bv[l * Dc + i - 2 * Dc];
    out[l * QS + i] = v;
}

// ---------------- block reductions ----------------
__device__ __forceinline__ float blockReduceSum(float v) {
    __shared__ float ws[32];
    int lane = threadIdx.x & 31, w = threadIdx.x >> 5;
    #pragma unroll
    for (int o = 16; o; o >>= 1) v += __shfl_down_sync(0xffffffffu, v, o);
    if (lane == 0) ws[w] = v;
    __syncthreads();
    int nw = blockDim.x >> 5;
    v = (threadIdx.x < nw) ? ws[threadIdx.x] : 0.f;
    if (w == 0) {
        #pragma unroll
        for (int o = 16; o; o >>= 1) v += __shfl_down_sync(0xffffffffu, v, o);
        if (lane == 0) ws[0] = v;
    }
    __syncthreads();
    float r = ws[0];
    __syncthreads();
    return r;
}
__device__ __forceinline__ float blockReduceMax(float v) {
    __shared__ float wm[32];
    int lane = threadIdx.x & 31, w = threadIdx.x >> 5;
    #pragma unroll
    for (int o = 16; o; o >>= 1) v = fmaxf(v, __shfl_down_sync(0xffffffffu, v, o));
    if (lane == 0) wm[w] = v;
    __syncthreads();
    int nw = blockDim.x >> 5;
    v = (threadIdx.x < nw) ? wm[threadIdx.x] : -FLT_MAX;
    if (w == 0) {
        #pragma unroll
        for (int o = 16; o; o >>= 1) v = fmaxf(v, __shfl_down_sync(0xffffffffu, v, o));
        if (lane == 0) wm[0] = v;
    }
    __syncthreads();
    float r = wm[0];
    __syncthreads();
    return r;
}

// ---------------- small kernels ----------------
__global__ void delta_kernel(const int* __restrict__ actions,
                             const float* __restrict__ action_emb,
                             const float* __restrict__ lie_w,
                             const float* __restrict__ lie_b,
                             float* __restrict__ delta) {
    int bt = blockIdx.x;
    __shared__ float emb[Dc];
    __shared__ float part[128];
    int a = actions[bt];
    const float* src = action_emb + (size_t)a * Dc;
    for (int i = threadIdx.x; i < Dc; i += blockDim.x) emb[i] = src[i];
    __syncthreads();
    int r = threadIdx.x & 31;
    int seg = threadIdx.x >> 5;
    float s = 0.f;
    int d0 = seg * 256;
    #pragma unroll 8
    for (int d = d0; d < d0 + 256; d++) s += emb[d] * lie_w[d * Rc + r];
    part[threadIdx.x] = s;
    __syncthreads();
    if (threadIdx.x < 32) {
        float v = part[threadIdx.x] + part[threadIdx.x + 32] +
                  part[threadIdx.x + 64] + part[threadIdx.x + 96];
        delta[(size_t)bt * Rc + threadIdx.x] = v + lie_b[threadIdx.x];
    }
}

__global__ void scan_kernel(const float* __restrict__ delta,
                            float* __restrict__ cosT, float* __restrict__ sinT) {
    int b = blockIdx.x / Rc, r = blockIdx.x % Rc;
    __shared__ float buf[2][Tc];
    int t = threadIdx.x;
    buf[0][t] = delta[((size_t)b * Tc + t) * Rc + r];
    __syncthreads();
    int src = 0;
    #pragma unroll
    for (int off = 1; off < Tc; off <<= 1) {
        float nv = buf[src][t];
        if (t >= off) nv += buf[src][t - off];
        buf[1 - src][t] = nv;
        src = 1 - src;
        __syncthreads();
    }
    float th = buf[src][t];
    size_t idx = ((size_t)b * Tc + t) * Rc + r;
    cosT[idx] = cosf(th);
    sinT[idx] = sinf(th);
}

__global__ void gather_kernel(const int* __restrict__ obs,
                              const float* __restrict__ emb,
                              float* __restrict__ x) {
    int bt = blockIdx.x;
    int o = obs[bt];
    const float4* s = (const float4*)(emb + (size_t)o * Dc);
    float4* d = (float4*)(x + (size_t)bt * Dc);
    d[threadIdx.x] = s[threadIdx.x];
}

__global__ void ln_kernel(const float* __restrict__ x,
                          const float* __restrict__ g,
                          const float* __restrict__ b,
                          uint32_t* __restrict__ ohi, uint32_t* __restrict__ olo) {
    int row = blockIdx.x;
    const float4* xr = (const float4*)(x + (size_t)row * Dc);
    float4 v = xr[threadIdx.x];
    float s = v.x + v.y + v.z + v.w;
    s = blockReduceSum(s);
    float mean = s * (1.f / Dc);
    float dx = v.x - mean, dy = v.y - mean, dz = v.z - mean, dw = v.w - mean;
    float s2 = dx*dx + dy*dy + dz*dz + dw*dw;
    s2 = blockReduceSum(s2);
    float rstd = rsqrtf(s2 * (1.f / Dc) + 1e-5f);
    float4 gv = ((const float4*)g)[threadIdx.x];
    float4 bv = ((const float4*)b)[threadIdx.x];
    float o0 = dx * rstd * gv.x + bv.x;
    float o1 = dy * rstd * gv.y + bv.y;
    float o2 = dz * rstd * gv.z + bv.z;
    float o3 = dw * rstd * gv.w + bv.w;
    uint32_t h0, l0, h1, l1;
    bsplit2(o0, o1, h0, l0);
    bsplit2(o2, o3, h1, l1);
    ((uint2*)(ohi + (size_t)row * 512))[threadIdx.x] = make_uint2(h0, h1);
    ((uint2*)(olo + (size_t)row * 512))[threadIdx.x] = make_uint2(l0, l1);
}

__global__ void rope_kernel(const float* __restrict__ cosT,
                            const float* __restrict__ sinT,
                            const float* __restrict__ QKV,
                            uint32_t* __restrict__ qhi, uint32_t* __restrict__ qlo,
                            uint32_t* __restrict__ khi, uint32_t* __restrict__ klo) {
    int idx = blockIdx.x * blockDim.x + threadIdx.x;
    if (idx >= Bc * Tc * Hc * Rc) return;
    int r = idx & 31;
    int hh = (idx >> 5) & 15;
    int bt = idx >> 9;
    float c = cosT[(size_t)bt * Rc + r];
    float s = sinT[(size_t)bt * Rc + r];
    size_t base = (size_t)bt * QS + hh * DHc + 2 * r;
    float2 q = *(const float2*)(QKV + base);
    float2 k = *(const float2*)(QKV + base + Dc);
    float qx = c * q.x - s * q.y, qy = s * q.x + c * q.y;
    float kx = c * k.x - s * k.y, ky = s * k.x + c * k.y;
    size_t pi = (size_t)bt * 512 + hh * 32 + r;
    uint32_t hi, lo;
    bsplit2(qx, qy, hi, lo);  qhi[pi] = hi; qlo[pi] = lo;
    bsplit2(kx, ky, hi, lo);  khi[pi] = hi; klo[pi] = lo;
}

__global__ void softmax_kernel(const float* __restrict__ scores,
                               uint32_t* __restrict__ ohi, uint32_t* __restrict__ olo) {
    int row = blockIdx.x;
    int t = row & (Tc - 1);
    const float* p = scores + (size_t)row * Tc;
    int valid = t + 1;
    int lastStore = ((t >> 7) + 1) << 7;
    int base = threadIdx.x * 4;
    float vals[4] = {0.f, 0.f, 0.f, 0.f};
    if (base < valid) {
        float4 v = ((const float4*)p)[threadIdx.x];
        vals[0] = v.x; vals[1] = v.y; vals[2] = v.z; vals[3] = v.w;
    }
    float m = -FLT_MAX;
    #pragma unroll
    for (int c = 0; c < 4; c++) {
        vals[c] = (base + c < valid) ? vals[c] * 0.125f : -FLT_MAX;
        m = fmaxf(m, vals[c]);
    }
    m = blockReduceMax(m);
    float s = 0.f;
    #pragma unroll
    for (int c = 0; c < 4; c++) {
        vals[c] = (base + c < valid) ? __expf(vals[c] - m) : 0.f;
        s += vals[c];
    }
    s = blockReduceSum(s);
    float inv = 1.f / s;
    if (base < lastStore) {
        uint32_t h0, l0, h1, l1;
        bsplit2(vals[0] * inv, vals[1] * inv, h0, l0);
        bsplit2(vals[2] * inv, vals[3] * inv, h1, l1);
        ((uint2*)(ohi + (size_t)row * 512))[threadIdx.x] = make_uint2(h0, h1);
        ((uint2*)(olo + (size_t)row * 512))[threadIdx.x] = make_uint2(l0, l1);
    }
}

// ---------------- host launcher ----------------
template<typename T>
static T* symaddr(const void* sym) {
    void* p = nullptr;
    cudaGetSymbolAddress(&p, sym);
    return (T*)p;
}

extern "C" void kernel_launch(void* const* d_in, const int* in_sizes, int n_in,
                              void* d_out, int out_size) {
    const int*   actions      = (const int*)  d_in[0];
    const int*   observations = (const int*)  d_in[1];
    const float* action_emb   = (const float*)d_in[2];
    const float* obs_emb      = (const float*)d_in[3];
    const float* lie_w        = (const float*)d_in[4];
    const float* lie_b        = (const float*)d_in[5];
    const float* Wq  = (const float*)d_in[6];
    const float* bq  = (const float*)d_in[7];
    const float* Wk  = (const float*)d_in[8];
    const float* bk  = (const float*)d_in[9];
    const float* Wv  = (const float*)d_in[10];
    const float* bv  = (const float*)d_in[11];
    const float* Wo  = (const float*)d_in[12];
    const float* bo  = (const float*)d_in[13];
    const float* ln1_g = (const float*)d_in[14];
    const float* ln1_b = (const float*)d_in[15];
    const float* ln2_g = (const float*)d_in[16];
    const float* ln2_b = (const float*)d_in[17];
    const float* w1  = (const float*)d_in[18];
    const float* b1  = (const float*)d_in[19];
    const float* w2  = (const float*)d_in[20];
    const float* b2  = (const float*)d_in[21];
    const float* out_g   = (const float*)d_in[22];
    const float* out_bln = (const float*)d_in[23];
    const float* out_w   = (const float*)d_in[24];
    const float* out_b   = (const float*)d_in[25];
    (void)in_sizes; (void)n_in; (void)out_size;

    float* dlt  = symaddr<float>(g_delta);
    float* cT   = symaddr<float>(g_cos);
    float* sT   = symaddr<float>(g_sin);
    float* x    = symaddr<float>(g_x);
    float* qkv  = symaddr<float>(g_qkv);
    float* sc   = symaddr<float>(g_sc);
    float* bqkv = symaddr<float>(g_bqkv);
    uint32_t* hhi = symaddr<uint32_t>(g_hhi);
    uint32_t* hlo = symaddr<uint32_t>(g_hlo);
    uint32_t* qhi = symaddr<uint32_t>(g_qhi);
    uint32_t* qlo = symaddr<uint32_t>(g_qlo);
    uint32_t* khi = symaddr<uint32_t>(g_khi);
    uint32_t* klo = symaddr<uint32_t>(g_klo);
    uint32_t* vthi = symaddr<uint32_t>(g_vthi);
    uint32_t* vtlo = symaddr<uint32_t>(g_vtlo);
    uint32_t* schi = symaddr<uint32_t>(g_schi);
    uint32_t* sclo = symaddr<uint32_t>(g_sclo);
    uint32_t* ohi = symaddr<uint32_t>(g_ohi);
    uint32_t* olo = symaddr<uint32_t>(g_olo);
    uint32_t* ffhi = symaddr<uint32_t>(g_ffhi);
    uint32_t* fflo = symaddr<uint32_t>(g_fflo);
    uint32_t* whi = symaddr<uint32_t>(g_whi);
    uint32_t* wlo = symaddr<uint32_t>(g_wlo);

    const int SMB128 = (4 * 128 * 12 + 4 * 128 * 12) * 4;  // 49152
    const int SMB64  = (4 * 128 * 12 + 4 * 64 * 12) * 4;   // 36864

    cudaFuncSetAttribute(mma_gemm<128,0,false,false>, cudaFuncAttributeMaxDynamicSharedMemorySize, SMB128);
    cudaFuncSetAttribute(mma_gemm<128,1,false,false>, cudaFuncAttributeMaxDynamicSharedMemorySize, SMB128);
    cudaFuncSetAttribute(mma_gemm<128,2,false,false>, cudaFuncAttributeMaxDynamicSharedMemorySize, SMB128);
    cudaFuncSetAttribute(mma_gemm<128,0,true,false>,  cudaFuncAttributeMaxDynamicSharedMemorySize, SMB128);
    cudaFuncSetAttribute(mma_gemm<64,3,false,true>,   cudaFuncAttributeMaxDynamicSharedMemorySize, SMB64);

    dim3 tb(8, 32);
    for (int l = 0; l < Lc; l++) {
        size_t wb = WPL(l);
        tsplit_kernel<<<dim3(32, 32), tb>>>(Wq + (size_t)l*DD, whi + wb,              wlo + wb,              Dc, Dc);
        tsplit_kernel<<<dim3(32, 32), tb>>>(Wk + (size_t)l*DD, whi + wb + 1024*512,   wlo + wb + 1024*512,   Dc, Dc);
        tsplit_kernel<<<dim3(32, 32), tb>>>(Wv + (size_t)l*DD, whi + wb + 2048*512,   wlo + wb + 2048*512,   Dc, Dc);
        tsplit_kernel<<<dim3(32, 32), tb>>>(Wo + (size_t)l*DD, whi + wb + P_WO,       wlo + wb + P_WO,       Dc, Dc);
        tsplit_kernel<<<dim3(128,32), tb>>>(w1 + (size_t)l*Dc*FFc, whi + wb + P_W1,   wlo + wb + P_W1,       Dc, FFc);
        tsplit_kernel<<<dim3(32,128), tb>>>(w2 + (size_t)l*FFc*Dc, whi + wb + P_W2,   wlo + wb + P_W2,       FFc, Dc);
    }
    tsplit_kernel<<<dim3(512, 32), tb>>>(out_w, whi + P_OUT, wlo + P_OUT, Dc, OVc);
    packbias_kernel<<<dim3(12, Lc), 256>>>(bq, bk, bv, bqkv);

    delta_kernel<<<BT, 128>>>(actions, action_emb, lie_w, lie_b, dlt);
    scan_kernel<<<Bc * Rc, Tc>>>(dlt, cT, sT);
    gather_kernel<<<BT, 256>>>(observations, obs_emb, x);

    for (int l = 0; l < Lc; l++) {
        size_t wb = WPL(l);
        ln_kernel<<<BT, 256>>>(x, ln1_g + l * Dc, ln1_b + l * Dc, hhi, hlo);

        dim3 gQ(QS / 128, BT / 128, 1);
        mma_gemm<128,0,false,false><<<gQ, 256, SMB128>>>(hhi, hlo, whi + wb, wlo + wb,
            bqkv + l*QS, nullptr, qkv, nullptr, nullptr,
            BT, QS, Dc, 512, 512, QS, 1, 0,0,0,0,0,0);

        rope_kernel<<<(Bc*Tc*Hc*Rc) / 256, 256>>>(cT, sT, qkv, qhi, qlo, khi, klo);
        vtrans_kernel<<<dim3(Tc/32, 2, Bc*Hc), tb>>>(qkv, vthi, vtlo);

        dim3 gS(Tc / 128, Tc / 128, Bc * Hc);
        mma_gemm<128,0,true,false><<<gS, 256, SMB128>>>(qhi, qlo, khi, klo,
            nullptr, nullptr, sc, nullptr, nullptr,
            Tc, Tc, DHc, 512, 512, Tc,
            Hc, (long long)Tc*512, 32, (long long)Tc*512, 32,
                (long long)Hc*Tc*Tc, (long long)Tc*Tc);

        softmax_kernel<<<Bc * Hc * Tc, 256>>>(sc, schi, sclo);

        dim3 gA(1, Tc / 128, Bc * Hc);
        mma_gemm<64,3,false,true><<<gA, 256, SMB64>>>(schi, sclo, vthi, vtlo,
            nullptr, nullptr, nullptr, ohi, olo,
            Tc, DHc, Tc, 512, 512, 512,
            Hc, (long long)Hc*Tc*512, (long long)Tc*512,
                (long long)Hc*DHc*512, (long long)DHc*512,
                (long long)Tc*512, 32);

        dim3 gP(Dc / 128, BT / 128, 1);
        mma_gemm<128,1,false,false><<<gP, 256, SMB128>>>(ohi, olo, whi + wb + P_WO, wlo + wb + P_WO,
            bo + l*Dc, x, x, nullptr, nullptr,
            BT, Dc, Dc, 512, 512, Dc, 1, 0,0,0,0,0,0);

        ln_kernel<<<BT, 256>>>(x, ln2_g + l * Dc, ln2_b + l * Dc, hhi, hlo);

        dim3 gF1(FFc / 128, BT / 128, 1);
        mma_gemm<128,2,false,false><<<gF1, 256, SMB128>>>(hhi, hlo, whi + wb + P_W1, wlo + wb + P_W1,
            b1 + l*FFc, nullptr, nullptr, ffhi, fflo,
            BT, FFc, Dc, 512, 512, 2048, 1, 0,0,0,0,0,0);

        dim3 gF2(Dc / 128, BT / 128, 1);
        mma_gemm<128,1,false,false><<<gF2, 256, SMB128>>>(ffhi, fflo, whi + wb + P_W2, wlo + wb + P_W2,
            b2 + l*Dc, x, x, nullptr, nullptr,
            BT, Dc, FFc, 2048, 2048, Dc, 1, 0,0,0,0,0,0);
    }

    ln_kernel<<<BT, 256>>>(x, out_g, out_bln, hhi, hlo);
    dim3 gO(OVc / 128, BT / 128, 1);
    mma_gemm<128,0,false,false><<<gO, 256, SMB128>>>(hhi, hlo, whi + P_OUT, wlo + P_OUT,
        out_b, nullptr, (float*)d_out, nullptr, nullptr,
        BT, OVc, Dc, 512, 512, OVc, 1, 0,0,0,0,0,0);
}

// round 12
// speedup vs baseline: 1.3976x; 1.3976x over previous
#include <cuda_runtime.h>
#include <cuda_fp16.h>
#include <cstdint>
#include <cfloat>
#include <math.h>

#define Bc 2
#define Tc 1024
#define Dc 1024
#define Hc 16
#define DHc 64
#define Rc 32
#define Lc 2
#define FFc 4096
#define OVc 16384
#define QS 3072
#define BT (Bc*Tc)
#define DD (Dc*Dc)

// ---------------- static device scratch ----------------
__device__ float g_delta[Bc*Tc*Rc];
__device__ float g_cos[Bc*Tc*Rc];
__device__ float g_sin[Bc*Tc*Rc];
__device__ float g_x  [BT*Dc];
__device__ float g_qkv[BT*QS];
__device__ float g_sc [(size_t)Bc*Hc*Tc*Tc];     // fp32 scores

// packed fp16x2 operand arrays (pair = 2 consecutive K elements)
__device__ uint32_t g_hhi[BT*512],  g_hlo[BT*512];      // ln out (A side: hi+lo)
__device__ uint32_t g_qhi[BT*512],  g_qlo[BT*512];      // rotated Q (A side)
__device__ uint32_t g_khi[BT*512],  g_klo[BT*512];      // rotated K (B side of scores, 3-term)
__device__ uint32_t g_vthi[Bc*Hc*DHc*512];              // V^T (B side, hi only)
__device__ uint32_t g_schi[(size_t)Bc*Hc*Tc*512], g_sclo[(size_t)Bc*Hc*Tc*512];
__device__ uint32_t g_ohi[BT*512],  g_olo[BT*512];
__device__ uint32_t g_ffhi[BT*2048], g_fflo[BT*2048];
__device__ uint32_t g_whi[20*DD];                       // all weights, transposed, hi only
__device__ float    g_bqkv[Lc*QS];

#define P_QKV 0
#define P_WO  ((size_t)3072*512)
#define P_W1  (P_WO + (size_t)1024*512)
#define P_W2  (P_W1 + (size_t)4096*512)
#define PL_SZ (P_W2 + (size_t)1024*2048)
#define P_OUT (2*PL_SZ)
#define WPL(l) ((size_t)(l)*PL_SZ)

// ---------------- helpers ----------------
__device__ __forceinline__ uint32_t smem_u32(const void* p) {
    uint32_t a;
    asm("{ .reg .u64 t; cvta.to.shared.u64 t, %1; cvt.u32.u64 %0, t; }" : "=r"(a) : "l"(p));
    return a;
}
// fp16 split: x ~= hi + lo per element (packed x2)
__device__ __forceinline__ void hsplit2(float x0, float x1, uint32_t& hi, uint32_t& lo) {
    __half2 h = __floats2half2_rn(x0, x1);
    hi = *reinterpret_cast<uint32_t*>(&h);
    float r0 = x0 - __low2float(h);
    float r1 = x1 - __high2float(h);
    __half2 l = __floats2half2_rn(r0, r1);
    lo = *reinterpret_cast<uint32_t*>(&l);
}
__device__ __forceinline__ uint32_t hround2(float x0, float x1) {
    __half2 h = __floats2half2_rn(x0, x1);
    return *reinterpret_cast<uint32_t*>(&h);
}
__device__ __forceinline__ void cp16(uint32_t dst, const void* src) {
    asm volatile("cp.async.cg.shared.global [%0], [%1], 16;" :: "r"(dst), "l"(src) : "memory");
}
#define CP_COMMIT() asm volatile("cp.async.commit_group;" ::: "memory")
#define CP_WAIT1()  asm volatile("cp.async.wait_group 1;" ::: "memory")
#define CP_WAIT0()  asm volatile("cp.async.wait_group 0;" ::: "memory")

#define MMA16(d, a, b) \
    asm volatile("mma.sync.aligned.m16n8k16.row.col.f32.f16.f16.f32 " \
        "{%0,%1,%2,%3}, {%4,%5,%6,%7}, {%8,%9}, {%0,%1,%2,%3};" \
        : "+f"((d)[0]), "+f"((d)[1]), "+f"((d)[2]), "+f"((d)[3]) \
        : "r"((a)[0]), "r"((a)[1]), "r"((a)[2]), "r"((a)[3]), "r"((b)[0]), "r"((b)[1]))

// ================= split-fp16 mma.sync GEMM =================
// C[M,N] = A[M,K] * Bt[N,K]^T. A packed fp16x2 hi/lo; B hi (+lo if TERMS==3).
// Strides in PAIR units. 128 x NT tiles, K-chunk 16, double-buffered cp.async.
// TERMS 2: acc += ah*bh + al*bh | TERMS 3: + ah*bl
// MODE 0: fp32 out (+bias if non-null) | 1: fp32 +bias+residual
//      2: packed gelu(+bias) out      | 3: packed plain out
// CSKIP: skip tiles above diagonal. CKLIM: clamp K at bm+128.
template<int NT, int MODE, int TERMS, bool CSKIP, bool CKLIM>
__global__ void __launch_bounds__(256)
mma_gemm(const uint32_t* __restrict__ AhG, const uint32_t* __restrict__ AlG,
         const uint32_t* __restrict__ BhG, const uint32_t* __restrict__ BlG,
         const float* __restrict__ bias, const float* __restrict__ Res,
         float* __restrict__ C, uint32_t* __restrict__ Chi, uint32_t* __restrict__ Clo,
         int M, int N, int K, int ldaP, int ldbP, int ldc,
         int H2, long long sAb, long long sAh, long long sBb, long long sBh,
         long long sCb, long long sCh)
{
    int bm = blockIdx.y * 128, bn = blockIdx.x * NT;
    if (CSKIP && bn > bm) return;

    int z = blockIdx.z;
    int zb = z / H2, zh = z % H2;
    AhG += zb * sAb + zh * sAh;  AlG += zb * sAb + zh * sAh;
    BhG += zb * sBb + zh * sBh;
    if (TERMS == 3) BlG += zb * sBb + zh * sBh;
    const float* R0 = nullptr;
    if (MODE == 0 || MODE == 1) {
        C += zb * sCb + zh * sCh;
        if (MODE == 1) R0 = Res + zb * sCb + zh * sCh;
    } else {
        Chi += zb * sCb + zh * sCh;
        Clo += zb * sCb + zh * sCh;
    }

    extern __shared__ uint32_t sm[];
    const int AST = 128 * 12;
    const int BST = NT * 12;
    uint32_t* AsHi = sm;
    uint32_t* AsLo = sm + 2 * AST;
    uint32_t* BsHi = sm + 4 * AST;
    uint32_t* BsLo = BsHi + 2 * BST;     // only when TERMS==3

    int tid = threadIdx.x;
    int w = tid >> 5, lane = tid & 31;
    int wm = w & 1, wn = w >> 1;
    int g = lane >> 2, tg = lane & 3;
    const int NTILES = NT / 32;

    int Keff = K;
    if (CKLIM) { int kl = bm + 128; Keff = (kl < K) ? kl : K; }
    int NCH = Keff >> 4;

    float acc[4][NTILES][4];
    #pragma unroll
    for (int i = 0; i < 4; i++)
        #pragma unroll
        for (int j = 0; j < NTILES; j++)
            #pragma unroll
            for (int e = 0; e < 4; e++) acc[i][j][e] = 0.f;

    auto copy_chunk = [&](int c, int s) {
        int row = tid >> 1, seg = tid & 1;
        size_t ga = (size_t)(bm + row) * ldaP + c * 8 + seg * 4;
        uint32_t da = s * AST + row * 12 + seg * 4;
        cp16(smem_u32(AsHi + da), AhG + ga);
        cp16(smem_u32(AsLo + da), AlG + ga);
        if (NT == 128 || tid < 2 * NT) {
            size_t gb = (size_t)(bn + row) * ldbP + c * 8 + seg * 4;
            uint32_t db = s * BST + row * 12 + seg * 4;
            cp16(smem_u32(BsHi + db), BhG + gb);
            if (TERMS == 3) cp16(smem_u32(BsLo + db), BlG + gb);
        }
        CP_COMMIT();
    };

    copy_chunk(0, 0);
    if (NCH > 1) copy_chunk(1, 1);

    for (int c = 0; c < NCH; c++) {
        if (c + 1 < NCH) { CP_WAIT1(); } else { CP_WAIT0(); }
        __syncthreads();
        int s = c & 1;
        const uint32_t* AH = AsHi + s * AST;
        const uint32_t* AL = AsLo + s * AST;
        const uint32_t* BH = BsHi + s * BST;
        const uint32_t* BL = BsLo + s * BST;

        uint32_t ah[4][4], al[4][4];
        #pragma unroll
        for (int mt = 0; mt < 4; mt++) {
            int r0 = wm * 64 + mt * 16 + g;
            ah[mt][0] = AH[r0 * 12 + tg];
            ah[mt][1] = AH[(r0 + 8) * 12 + tg];
            ah[mt][2] = AH[r0 * 12 + tg + 4];
            ah[mt][3] = AH[(r0 + 8) * 12 + tg + 4];
            al[mt][0] = AL[r0 * 12 + tg];
            al[mt][1] = AL[(r0 + 8) * 12 + tg];
            al[mt][2] = AL[r0 * 12 + tg + 4];
            al[mt][3] = AL[(r0 + 8) * 12 + tg + 4];
        }
        uint32_t bh[NTILES][2], bl[NTILES][2];
        #pragma unroll
        for (int nt = 0; nt < NTILES; nt++) {
            int n0 = wn * (NT / 4) + nt * 8 + g;
            bh[nt][0] = BH[n0 * 12 + tg];
            bh[nt][1] = BH[n0 * 12 + tg + 4];
            if (TERMS == 3) {
                bl[nt][0] = BL[n0 * 12 + tg];
                bl[nt][1] = BL[n0 * 12 + tg + 4];
            }
        }
        #pragma unroll
        for (int mt = 0; mt < 4; mt++)
            #pragma unroll
            for (int nt = 0; nt < NTILES; nt++) {
                MMA16(acc[mt][nt], al[mt], bh[nt]);
                if (TERMS == 3) MMA16(acc[mt][nt], ah[mt], bl[nt]);
                MMA16(acc[mt][nt], ah[mt], bh[nt]);
            }
        __syncthreads();
        if (c + 2 < NCH) copy_chunk(c + 2, s);
    }

    // -------- epilogue --------
    #pragma unroll
    for (int mt = 0; mt < 4; mt++) {
        #pragma unroll
        for (int nt = 0; nt < NTILES; nt++) {
            int row0 = bm + wm * 64 + mt * 16 + g;
            int col  = bn + wn * (NT / 4) + nt * 8 + tg * 2;
            #pragma unroll
            for (int half = 0; half < 2; half++) {
                int row = row0 + half * 8;
                float v0 = acc[mt][nt][half * 2 + 0];
                float v1 = acc[mt][nt][half * 2 + 1];
                if (MODE == 1 || MODE == 2 || (MODE == 0 && bias)) {
                    float2 bv = *(const float2*)(bias + col);
                    v0 += bv.x; v1 += bv.y;
                }
                if (MODE == 1) {
                    float2 rr = *(const float2*)(R0 + (size_t)row * ldc + col);
                    v0 += rr.x; v1 += rr.y;
                }
                if (MODE == 2) {
                    v0 = 0.5f * v0 * (1.f + erff(v0 * 0.70710678118654752f));
                    v1 = 0.5f * v1 * (1.f + erff(v1 * 0.70710678118654752f));
                }
                if (MODE == 0 || MODE == 1) {
                    float2 o = {v0, v1};
                    *(float2*)(C + (size_t)row * ldc + col) = o;
                } else {
                    uint32_t hi, lo;
                    hsplit2(v0, v1, hi, lo);
                    size_t ci = (size_t)row * ldc + (col >> 1);
                    Chi[ci] = hi;
                    Clo[ci] = lo;
                }
            }
        }
    }
}

// ---------------- weight transpose + fp16 round (hi only) ----------------
__global__ void wsplit_kernel(const float* __restrict__ in,
                              uint32_t* __restrict__ ohi,
                              int rows, int cols) {
    __shared__ float tile[32][33];
    int c0 = blockIdx.x * 32, r0 = blockIdx.y * 32;
    int x = threadIdx.x, y = threadIdx.y;
    float4 v = *(const float4*)(in + (size_t)(r0 + y) * cols + c0 + 4 * x);
    tile[y][4*x+0] = v.x; tile[y][4*x+1] = v.y; tile[y][4*x+2] = v.z; tile[y][4*x+3] = v.w;
    __syncthreads();
    int rowP = rows >> 1;
    uint32_t h0 = hround2(tile[4*x+0][y], tile[4*x+1][y]);
    uint32_t h1 = hround2(tile[4*x+2][y], tile[4*x+3][y]);
    size_t ob = (size_t)(c0 + y) * rowP + (r0 >> 1) + 2 * x;
    *(uint2*)(ohi + ob) = make_uint2(h0, h1);
}

// V inside fp32 qkv -> vt packed hi [(b*H+h)*64+d][t/2]
__global__ void vtrans_kernel(const float* __restrict__ qkv,
                              uint32_t* __restrict__ vthi) {
    __shared__ float tile[32][33];
    int z = blockIdx.z, b = z >> 4, hh = z & 15;
    int t0 = blockIdx.x * 32, d0 = blockIdx.y * 32;
    int x = threadIdx.x, y = threadIdx.y;
    float4 v = *(const float4*)(qkv + (size_t)(b * Tc + t0 + y) * QS + 2 * Dc + hh * DHc + d0 + 4 * x);
    tile[y][4*x+0] = v.x; tile[y][4*x+1] = v.y; tile[y][4*x+2] = v.z; tile[y][4*x+3] = v.w;
    __syncthreads();
    uint32_t h0 = hround2(tile[4*x+0][y], tile[4*x+1][y]);
    uint32_t h1 = hround2(tile[4*x+2][y], tile[4*x+3][y]);
    size_t ob = (size_t)(z * DHc + d0 + y) * 512 + (t0 >> 1) + 2 * x;
    *(uint2*)(vthi + ob) = make_uint2(h0, h1);
}

__global__ void packbias_kernel(const float* __restrict__ bq,
                                const float* __restrict__ bk,
                                const float* __restrict__ bv,
                                float* __restrict__ out) {
    int l = blockIdx.y;
    int i = blockIdx.x * 256 + threadIdx.x;
    float v = (i < Dc) ? bq[l * Dc + i] : (i < 2 * Dc) ? bk[l * Dc + i - Dc] : bv[l * Dc + i - 2 * Dc];
    out[l * QS + i] = v;
}

// ---------------- block reductions ----------------
__device__ __forceinline__ float blockReduceSum(float v) {
    __shared__ float ws[32];
    int lane = threadIdx.x & 31, w = threadIdx.x >> 5;
    #pragma unroll
    for (int o = 16; o; o >>= 1) v += __shfl_down_sync(0xffffffffu, v, o);
    if (lane == 0) ws[w] = v;
    __syncthreads();
    int nw = blockDim.x >> 5;
    v = (threadIdx.x < nw) ? ws[threadIdx.x] : 0.f;
    if (w == 0) {
        #pragma unroll
        for (int o = 16; o; o >>= 1) v += __shfl_down_sync(0xffffffffu, v, o);
        if (lane == 0) ws[0] = v;
    }
    __syncthreads();
    float r = ws[0];
    __syncthreads();
    return r;
}
__device__ __forceinline__ float blockReduceMax(float v) {
    __shared__ float wm[32];
    int lane = threadIdx.x & 31, w = threadIdx.x >> 5;
    #pragma unroll
    for (int o = 16; o; o >>= 1) v = fmaxf(v, __shfl_down_sync(0xffffffffu, v, o));
    if (lane == 0) wm[w] = v;
    __syncthreads();
    int nw = blockDim.x >> 5;
    v = (threadIdx.x < nw) ? wm[threadIdx.x] : -FLT_MAX;
    if (w == 0) {
        #pragma unroll
        for (int o = 16; o; o >>= 1) v = fmaxf(v, __shfl_down_sync(0xffffffffu, v, o));
        if (lane == 0) wm[0] = v;
    }
    __syncthreads();
    float r = wm[0];
    __syncthreads();
    return r;
}

// ---------------- small kernels ----------------
__global__ void delta_kernel(const int* __restrict__ actions,
                             const float* __restrict__ action_emb,
                             const float* __restrict__ lie_w,
                             const float* __restrict__ lie_b,
                             float* __restrict__ delta) {
    int bt = blockIdx.x;
    __shared__ float emb[Dc];
    __shared__ float part[128];
    int a = actions[bt];
    const float* src = action_emb + (size_t)a * Dc;
    for (int i = threadIdx.x; i < Dc; i += blockDim.x) emb[i] = src[i];
    __syncthreads();
    int r = threadIdx.x & 31;
    int seg = threadIdx.x >> 5;
    float s = 0.f;
    int d0 = seg * 256;
    #pragma unroll 8
    for (int d = d0; d < d0 + 256; d++) s += emb[d] * lie_w[d * Rc + r];
    part[threadIdx.x] = s;
    __syncthreads();
    if (threadIdx.x < 32) {
        float v = part[threadIdx.x] + part[threadIdx.x + 32] +
                  part[threadIdx.x + 64] + part[threadIdx.x + 96];
        delta[(size_t)bt * Rc + threadIdx.x] = v + lie_b[threadIdx.x];
    }
}

__global__ void scan_kernel(const float* __restrict__ delta,
                            float* __restrict__ cosT, float* __restrict__ sinT) {
    int b = blockIdx.x / Rc, r = blockIdx.x % Rc;
    __shared__ float buf[2][Tc];
    int t = threadIdx.x;
    buf[0][t] = delta[((size_t)b * Tc + t) * Rc + r];
    __syncthreads();
    int src = 0;
    #pragma unroll
    for (int off = 1; off < Tc; off <<= 1) {
        float nv = buf[src][t];
        if (t >= off) nv += buf[src][t - off];
        buf[1 - src][t] = nv;
        src = 1 - src;
        __syncthreads();
    }
    float th = buf[src][t];
    size_t idx = ((size_t)b * Tc + t) * Rc + r;
    cosT[idx] = cosf(th);
    sinT[idx] = sinf(th);
}

__global__ void gather_kernel(const int* __restrict__ obs,
                              const float* __restrict__ emb,
                              float* __restrict__ x) {
    int bt = blockIdx.x;
    int o = obs[bt];
    const float4* s = (const float4*)(emb + (size_t)o * Dc);
    float4* d = (float4*)(x + (size_t)bt * Dc);
    d[threadIdx.x] = s[threadIdx.x];
}

__global__ void ln_kernel(const float* __restrict__ x,
                          const float* __restrict__ g,
                          const float* __restrict__ b,
                          uint32_t* __restrict__ ohi, uint32_t* __restrict__ olo) {
    int row = blockIdx.x;
    const float4* xr = (const float4*)(x + (size_t)row * Dc);
    float4 v = xr[threadIdx.x];
    float s = v.x + v.y + v.z + v.w;
    s = blockReduceSum(s);
    float mean = s * (1.f / Dc);
    float dx = v.x - mean, dy = v.y - mean, dz = v.z - mean, dw = v.w - mean;
    float s2 = dx*dx + dy*dy + dz*dz + dw*dw;
    s2 = blockReduceSum(s2);
    float rstd = rsqrtf(s2 * (1.f / Dc) + 1e-5f);
    float4 gv = ((const float4*)g)[threadIdx.x];
    float4 bv = ((const float4*)b)[threadIdx.x];
    float o0 = dx * rstd * gv.x + bv.x;
    float o1 = dy * rstd * gv.y + bv.y;
    float o2 = dz * rstd * gv.z + bv.z;
    float o3 = dw * rstd * gv.w + bv.w;
    uint32_t h0, l0, h1, l1;
    hsplit2(o0, o1, h0, l0);
    hsplit2(o2, o3, h1, l1);
    ((uint2*)(ohi + (size_t)row * 512))[threadIdx.x] = make_uint2(h0, h1);
    ((uint2*)(olo + (size_t)row * 512))[threadIdx.x] = make_uint2(l0, l1);
}

__global__ void rope_kernel(const float* __restrict__ cosT,
                            const float* __restrict__ sinT,
                            const float* __restrict__ QKV,
                            uint32_t* __restrict__ qhi, uint32_t* __restrict__ qlo,
                            uint32_t* __restrict__ khi, uint32_t* __restrict__ klo) {
    int idx = blockIdx.x * blockDim.x + threadIdx.x;
    if (idx >= Bc * Tc * Hc * Rc) return;
    int r = idx & 31;
    int hh = (idx >> 5) & 15;
    int bt = idx >> 9;
    float c = cosT[(size_t)bt * Rc + r];
    float s = sinT[(size_t)bt * Rc + r];
    size_t base = (size_t)bt * QS + hh * DHc + 2 * r;
    float2 q = *(const float2*)(QKV + base);
    float2 k = *(const float2*)(QKV + base + Dc);
    float qx = c * q.x - s * q.y, qy = s * q.x + c * q.y;
    float kx = c * k.x - s * k.y, ky = s * k.x + c * k.y;
    size_t pi = (size_t)bt * 512 + hh * 32 + r;
    uint32_t hi, lo;
    hsplit2(qx, qy, hi, lo);  qhi[pi] = hi; qlo[pi] = lo;
    hsplit2(kx, ky, hi, lo);  khi[pi] = hi; klo[pi] = lo;
}

__global__ void softmax_kernel(const float* __restrict__ scores,
                               uint32_t* __restrict__ ohi, uint32_t* __restrict__ olo) {
    int row = blockIdx.x;
    int t = row & (Tc - 1);
    const float* p = scores + (size_t)row * Tc;
    int valid = t + 1;
    int lastStore = ((t >> 7) + 1) << 7;
    int base = threadIdx.x * 4;
    float vals[4] = {0.f, 0.f, 0.f, 0.f};
    if (base < valid) {
        float4 v = ((const float4*)p)[threadIdx.x];
        vals[0] = v.x; vals[1] = v.y; vals[2] = v.z; vals[3] = v.w;
    }
    float m = -FLT_MAX;
    #pragma unroll
    for (int c = 0; c < 4; c++) {
        vals[c] = (base + c < valid) ? vals[c] * 0.125f : -FLT_MAX;
        m = fmaxf(m, vals[c]);
    }
    m = blockReduceMax(m);
    float s = 0.f;
    #pragma unroll
    for (int c = 0; c < 4; c++) {
        vals[c] = (base + c < valid) ? __expf(vals[c] - m) : 0.f;
        s += vals[c];
    }
    s = blockReduceSum(s);
    float inv = 1.f / s;
    if (base < lastStore) {
        uint32_t h0, l0, h1, l1;
        hsplit2(vals[0] * inv, vals[1] * inv, h0, l0);
        hsplit2(vals[2] * inv, vals[3] * inv, h1, l1);
        ((uint2*)(ohi + (size_t)row * 512))[threadIdx.x] = make_uint2(h0, h1);
        ((uint2*)(olo + (size_t)row * 512))[threadIdx.x] = make_uint2(l0, l1);
    }
}

// ---------------- host launcher ----------------
template<typename T>
static T* symaddr(const void* sym) {
    void* p = nullptr;
    cudaGetSymbolAddress(&p, sym);
    return (T*)p;
}

extern "C" void kernel_launch(void* const* d_in, const int* in_sizes, int n_in,
                              void* d_out, int out_size) {
    const int*   actions      = (const int*)  d_in[0];
    const int*   observations = (const int*)  d_in[1];
    const float* action_emb   = (const float*)d_in[2];
    const float* obs_emb      = (const float*)d_in[3];
    const float* lie_w        = (const float*)d_in[4];
    const float* lie_b        = (const float*)d_in[5];
    const float* Wq  = (const float*)d_in[6];
    const float* bq  = (const float*)d_in[7];
    const float* Wk  = (const float*)d_in[8];
    const float* bk  = (const float*)d_in[9];
    const float* Wv  = (const float*)d_in[10];
    const float* bv  = (const float*)d_in[11];
    const float* Wo  = (const float*)d_in[12];
    const float* bo  = (const float*)d_in[13];
    const float* ln1_g = (const float*)d_in[14];
    const float* ln1_b = (const float*)d_in[15];
    const float* ln2_g = (const float*)d_in[16];
    const float* ln2_b = (const float*)d_in[17];
    const float* w1  = (const float*)d_in[18];
    const float* b1  = (const float*)d_in[19];
    const float* w2  = (const float*)d_in[20];
    const float* b2  = (const float*)d_in[21];
    const float* out_g   = (const float*)d_in[22];
    const float* out_bln = (const float*)d_in[23];
    const float* out_w   = (const float*)d_in[24];
    const float* out_b   = (const float*)d_in[25];
    (void)in_sizes; (void)n_in; (void)out_size;

    float* dlt  = symaddr<float>(g_delta);
    float* cT   = symaddr<float>(g_cos);
    float* sT   = symaddr<float>(g_sin);
    float* x    = symaddr<float>(g_x);
    float* qkv  = symaddr<float>(g_qkv);
    float* sc   = symaddr<float>(g_sc);
    float* bqkv = symaddr<float>(g_bqkv);
    uint32_t* hhi = symaddr<uint32_t>(g_hhi);
    uint32_t* hlo = symaddr<uint32_t>(g_hlo);
    uint32_t* qhi = symaddr<uint32_t>(g_qhi);
    uint32_t* qlo = symaddr<uint32_t>(g_qlo);
    uint32_t* khi = symaddr<uint32_t>(g_khi);
    uint32_t* klo = symaddr<uint32_t>(g_klo);
    uint32_t* vthi = symaddr<uint32_t>(g_vthi);
    uint32_t* schi = symaddr<uint32_t>(g_schi);
    uint32_t* sclo = symaddr<uint32_t>(g_sclo);
    uint32_t* ohi = symaddr<uint32_t>(g_ohi);
    uint32_t* olo = symaddr<uint32_t>(g_olo);
    uint32_t* ffhi = symaddr<uint32_t>(g_ffhi);
    uint32_t* fflo = symaddr<uint32_t>(g_fflo);
    uint32_t* whi = symaddr<uint32_t>(g_whi);

    // smem: A hi+lo (4*AST) + B hi (2*BST) [+ B lo (2*BST) if TERMS==3]
    const int SMT2_128 = (4 * 128 * 12 + 2 * 128 * 12) * 4;  // 36864
    const int SMT3_128 = (4 * 128 * 12 + 4 * 128 * 12) * 4;  // 49152
    const int SMT2_64  = (4 * 128 * 12 + 2 * 64 * 12) * 4;   // 30720

    cudaFuncSetAttribute(mma_gemm<128,0,2,false,false>, cudaFuncAttributeMaxDynamicSharedMemorySize, SMT2_128);
    cudaFuncSetAttribute(mma_gemm<128,1,2,false,false>, cudaFuncAttributeMaxDynamicSharedMemorySize, SMT2_128);
    cudaFuncSetAttribute(mma_gemm<128,2,2,false,false>, cudaFuncAttributeMaxDynamicSharedMemorySize, SMT2_128);
    cudaFuncSetAttribute(mma_gemm<128,0,3,true,false>,  cudaFuncAttributeMaxDynamicSharedMemorySize, SMT3_128);
    cudaFuncSetAttribute(mma_gemm<64,3,2,false,true>,   cudaFuncAttributeMaxDynamicSharedMemorySize, SMT2_64);

    dim3 tb(8, 32);
    for (int l = 0; l < Lc; l++) {
        size_t wb = WPL(l);
        wsplit_kernel<<<dim3(32, 32), tb>>>(Wq + (size_t)l*DD,     whi + wb,            Dc, Dc);
        wsplit_kernel<<<dim3(32, 32), tb>>>(Wk + (size_t)l*DD,     whi + wb + 1024*512, Dc, Dc);
        wsplit_kernel<<<dim3(32, 32), tb>>>(Wv + (size_t)l*DD,     whi + wb + 2048*512, Dc, Dc);
        wsplit_kernel<<<dim3(32, 32), tb>>>(Wo + (size_t)l*DD,     whi + wb + P_WO,     Dc, Dc);
        wsplit_kernel<<<dim3(128,32), tb>>>(w1 + (size_t)l*Dc*FFc, whi + wb + P_W1,     Dc, FFc);
        wsplit_kernel<<<dim3(32,128), tb>>>(w2 + (size_t)l*FFc*Dc, whi + wb + P_W2,     FFc, Dc);
    }
    wsplit_kernel<<<dim3(512, 32), tb>>>(out_w, whi + P_OUT, Dc, OVc);
    packbias_kernel<<<dim3(12, Lc), 256>>>(bq, bk, bv, bqkv);

    delta_kernel<<<BT, 128>>>(actions, action_emb, lie_w, lie_b, dlt);
    scan_kernel<<<Bc * Rc, Tc>>>(dlt, cT, sT);
    gather_kernel<<<BT, 256>>>(observations, obs_emb, x);

    for (int l = 0; l < Lc; l++) {
        size_t wb = WPL(l);
        ln_kernel<<<BT, 256>>>(x, ln1_g + l * Dc, ln1_b + l * Dc, hhi, hlo);

        dim3 gQ(QS / 128, BT / 128, 1);
        mma_gemm<128,0,2,false,false><<<gQ, 256, SMT2_128>>>(hhi, hlo, whi + wb, nullptr,
            bqkv + l*QS, nullptr, qkv, nullptr, nullptr,
            BT, QS, Dc, 512, 512, QS, 1, 0,0,0,0,0,0);

        rope_kernel<<<(Bc*Tc*Hc*Rc) / 256, 256>>>(cT, sT, qkv, qhi, qlo, khi, klo);
        vtrans_kernel<<<dim3(Tc/32, 2, Bc*Hc), tb>>>(qkv, vthi);

        // scores = Qr @ Kr^T  (3-term: K hi+lo; causal tiles only)
        dim3 gS(Tc / 128, Tc / 128, Bc * Hc);
        mma_gemm<128,0,3,true,false><<<gS, 256, SMT3_128>>>(qhi, qlo, khi, klo,
            nullptr, nullptr, sc, nullptr, nullptr,
            Tc, Tc, DHc, 512, 512, Tc,
            Hc, (long long)Tc*512, 32, (long long)Tc*512, 32,
                (long long)Hc*Tc*Tc, (long long)Tc*Tc);

        softmax_kernel<<<Bc * Hc * Tc, 256>>>(sc, schi, sclo);

        // o = attn @ V (2-term: V hi only; K clamped)
        dim3 gA(1, Tc / 128, Bc * Hc);
        mma_gemm<64,3,2,false,true><<<gA, 256, SMT2_64>>>(schi, sclo, vthi, nullptr,
            nullptr, nullptr, nullptr, ohi, olo,
            Tc, DHc, Tc, 512, 512, 512,
            Hc, (long long)Hc*Tc*512, (long long)Tc*512,
                (long long)Hc*DHc*512, (long long)DHc*512,
                (long long)Tc*512, 32);

        dim3 gP(Dc / 128, BT / 128, 1);
        mma_gemm<128,1,2,false,false><<<gP, 256, SMT2_128>>>(ohi, olo, whi + wb + P_WO, nullptr,
            bo + l*Dc, x, x, nullptr, nullptr,
            BT, Dc, Dc, 512, 512, Dc, 1, 0,0,0,0,0,0);

        ln_kernel<<<BT, 256>>>(x, ln2_g + l * Dc, ln2_b + l * Dc, hhi, hlo);

        dim3 gF1(FFc / 128, BT / 128, 1);
        mma_gemm<128,2,2,false,false><<<gF1, 256, SMT2_128>>>(hhi, hlo, whi + wb + P_W1, nullptr,
            b1 + l*FFc, nullptr, nullptr, ffhi, fflo,
            BT, FFc, Dc, 512, 512, 2048, 1, 0,0,0,0,0,0);

        dim3 gF2(Dc / 128, BT / 128, 1);
        mma_gemm<128,1,2,false,false><<<gF2, 256, SMT2_128>>>(ffhi, fflo, whi + wb + P_W2, nullptr,
            b2 + l*Dc, x, x, nullptr, nullptr,
            BT, Dc, FFc, 2048, 2048, Dc, 1, 0,0,0,0,0,0);
    }

    ln_kernel<<<BT, 256>>>(x, out_g, out_bln, hhi, hlo);
    dim3 gO(OVc / 128, BT / 128, 1);
    mma_gemm<128,0,2,false,false><<<gO, 256, SMT2_128>>>(hhi, hlo, whi + P_OUT, nullptr,
        out_b, nullptr, (float*)d_out, nullptr, nullptr,
        BT, OVc, Dc, 512, 512, OVc, 1, 0,0,0,0,0,0);
}